// round 13
// baseline (speedup 1.0000x reference)
#include <cuda_runtime.h>
#include <cuda_fp16.h>
#include <cstdint>

// Problem constants
#define BB   16
#define CIN  64
#define COUT 64
#define HH   128
#define WW   128
#define NKW  36864
#define AWN  36928

// ---------------------------------------------------------------------------
// Device scratch (allocation-free rule)
// ---------------------------------------------------------------------------
__device__ float  g_bias[BB * COUT];
__device__ __half g_xh[BB * HH * WW * CIN];   // NHWC fp16
__device__ __half g_wh[BB * 9 * COUT * CIN];  // [b][tap][co][ci] fp16

// ---------------------------------------------------------------------------
// Helpers (family-agnostic: ldmatrix + mma.sync + cp.async, sm_80+)
// ---------------------------------------------------------------------------
__device__ __forceinline__ uint32_t smem_u32(const void* p) {
    uint32_t a;
    asm("{ .reg .u64 t; cvta.to.shared.u64 t, %1; cvt.u32.u64 %0, t; }" : "=r"(a) : "l"(p));
    return a;
}
__device__ __forceinline__ void ldsm4(uint32_t (&r)[4], uint32_t addr) {
    asm volatile("ldmatrix.sync.aligned.m8n8.x4.shared.b16 {%0,%1,%2,%3}, [%4];"
                 : "=r"(r[0]), "=r"(r[1]), "=r"(r[2]), "=r"(r[3]) : "r"(addr));
}
__device__ __forceinline__ void mma16816(float (&d)[4], const uint32_t (&a)[4],
                                         uint32_t b0, uint32_t b1) {
    asm volatile(
        "mma.sync.aligned.m16n8k16.row.col.f32.f16.f16.f32 "
        "{%0,%1,%2,%3}, {%4,%5,%6,%7}, {%8,%9}, {%0,%1,%2,%3};"
        : "+f"(d[0]), "+f"(d[1]), "+f"(d[2]), "+f"(d[3])
        : "r"(a[0]), "r"(a[1]), "r"(a[2]), "r"(a[3]), "r"(b0), "r"(b1));
}
__device__ __forceinline__ void cp16(uint32_t dst, const void* src, int sz) {
    asm volatile("cp.async.cg.shared.global [%0], [%1], 16, %2;"
                 :: "r"(dst), "l"(src), "r"(sz) : "memory");
}
#define CP_COMMIT() asm volatile("cp.async.commit_group;" ::: "memory")
#define CP_WAIT0()  asm volatile("cp.async.wait_group 0;" ::: "memory")

// ---------------------------------------------------------------------------
// Fused prep kernel: blocks [0,2048) transpose/pack x; blocks [2048,2193)
// run the MLP and pack weights + biases. Independent work, one launch.
// ---------------------------------------------------------------------------
__global__ __launch_bounds__(256) void prep_kernel(const float* __restrict__ x,
                                                   const float* __restrict__ z,
                                                   const float* __restrict__ W0,
                                                   const float* __restrict__ b0,
                                                   const float* __restrict__ W1,
                                                   const float* __restrict__ b1,
                                                   const float* __restrict__ W2,
                                                   const float* __restrict__ b2) {
    const int tid = threadIdx.x;

    if (blockIdx.x < 2048) {
        // ---- pack x: NCHW f32 -> NHWC fp16 (smem transpose) ----
        __shared__ float s[64][129];
        const int b = blockIdx.x >> 7;
        const int y = blockIdx.x & 127;
        const int px = tid & 127, hh = tid >> 7;
        #pragma unroll
        for (int it = 0; it < 32; ++it) {
            const int ci = it * 2 + hh;
            s[ci][px] = x[((size_t)(b * 64 + ci) * HH + y) * WW + px];
        }
        __syncthreads();
        const int ci2 = tid & 63, pg = tid >> 6;
        #pragma unroll
        for (int it = 0; it < 32; ++it) {
            const int p2 = it * 4 + pg;
            g_xh[((size_t)(b * HH + y) * WW + p2) * 64 + ci2] =
                __float2half_rn(s[ci2][p2]);
        }
        return;
    }

    // ---- MLP + weight pack ----
    __shared__ float sz[BB * 16];
    __shared__ float h0[BB * 20];
    __shared__ float sh[BB * 30];

    sz[tid] = z[tid];
    __syncthreads();
    for (int e = tid; e < BB * 20; e += 256) {
        const int b = e / 20, u = e % 20;
        float s = b0[u];
        #pragma unroll
        for (int j = 0; j < 16; ++j) s += sz[b * 16 + j] * W0[u * 16 + j];
        h0[e] = fmaxf(s, 0.0f);
    }
    __syncthreads();
    for (int e = tid; e < BB * 30; e += 256) {
        const int b = e / 30, u = e % 30;
        float s = b1[u];
        #pragma unroll
        for (int j = 0; j < 20; ++j) s += h0[b * 20 + j] * W1[u * 20 + j];
        sh[e] = fmaxf(s, 0.0f);
    }
    __syncthreads();

    const int i = (blockIdx.x - 2048) * 256 + tid;
    if (i >= AWN) return;
    float w[30];
    #pragma unroll
    for (int j = 0; j < 30; ++j) w[j] = W2[i * 30 + j];
    const float bias = b2[i];

    if (i < NKW) {
        const int co  = i / 576;
        const int rem = i % 576;
        const int ci  = rem / 9;
        const int s9  = rem % 9;
        #pragma unroll
        for (int b = 0; b < BB; ++b) {
            float s = bias;
            #pragma unroll
            for (int j = 0; j < 30; ++j) s += sh[b * 30 + j] * w[j];
            g_wh[((size_t)(b * 9 + s9) * 64 + co) * 64 + ci] =
                __float2half_rn(fmaxf(s, 0.0f));
        }
    } else {
        const int co = i - NKW;
        #pragma unroll
        for (int b = 0; b < BB; ++b) {
            float s = bias;
            #pragma unroll
            for (int j = 0; j < 30; ++j) s += sh[b * 30 + j] * w[j];
            g_bias[b * 64 + co] = fmaxf(s, 0.0f);
        }
    }
}

// ---------------------------------------------------------------------------
// Conv, persistent-slab, rolling 7-slot x ring, fully prefetched.
// Grid: (8 slabs, 16 batch), 512 threads, 4 tiles of 4 output rows each.
// Warp = 64 px x 32 co (mt=4, pr=2). Weights (72KB, 9 taps) resident.
// Schedule: kh0 prefetches ty+3, kh1 -> ty+4, kh2 -> ty+5 & ty+6; next
// tile's kh0 window is fully staged => no synchronous row loads in
// steady state. slot(row) = (row+1) % 7; per-phase write slots verified
// disjoint from the 4-slot read set.
// ---------------------------------------------------------------------------
#define W_SMEM  73728                       // 9 taps * 8KB
#define X_TILE  16640                       // 130 rows * 128B
#define NSLOT   7
#define SM_TOTAL (W_SMEM + NSLOT * X_TILE)  // 190208

__global__ __launch_bounds__(512, 1) void conv_mma_kernel(float* __restrict__ out) {
    extern __shared__ char smem[];
    char* wptr = smem;
    char* xptr = smem + W_SMEM;
    const uint32_t wbase = smem_u32(wptr);
    const uint32_t xbase = smem_u32(xptr);

    const int tid  = threadIdx.x;
    const int wid  = tid >> 5;
    const int lane = tid & 31;
    const int slab = blockIdx.x;            // 0..7
    const int b    = blockIdx.y;
    const int ty0  = slab * 16;

    // ---- row stager: one image row -> ring slot, zero-fill OOB ----
    auto stage_row = [&](int rowimg) {
        const uint32_t slot = (uint32_t)((rowimg + 1) % NSLOT);
        const uint32_t sdst = xbase + slot * X_TILE;
        const int rc = min(max(rowimg, 0), HH - 1);
        for (int e = tid; e < 1040; e += 512) {
            const int r  = e >> 3;
            const int c  = e & 7;
            const int px = r - 1;
            const int pc = min(max(px, 0), WW - 1);
            const int sz = ((unsigned)rowimg < (unsigned)HH &&
                            (unsigned)px < (unsigned)WW) ? 16 : 0;
            const __half* src = g_xh + (((size_t)(b * HH + rc) * WW + pc) * 64 + c * 8);
            const uint32_t off = r * 128 + ((c * 16) ^ ((r & 7) * 16));
            cp16(sdst + off, src, sz);
        }
        CP_COMMIT();
    };

    // ---- stage ALL weights once (9 taps), swizzled [row=co][128B] ----
    for (int e = tid; e < 4608; e += 512) {
        const int chunk = e & 7;
        const int co    = (e >> 3) & 63;
        const int tap   = e >> 9;
        const __half* src = g_wh +
            (((size_t)(b * 9 + tap) * 64 + co) * 64 + chunk * 8);
        const uint32_t off = co * 128 + ((chunk * 16) ^ ((co & 7) * 16));
        *reinterpret_cast<uint4*>(wptr + tap * 8192 + off) =
            *reinterpret_cast<const uint4*>(src);
    }

    // prologue: rows ty0-1 .. ty0+2 in flight
    stage_row(ty0 - 1);
    stage_row(ty0);
    stage_row(ty0 + 1);
    stage_row(ty0 + 2);

    // ---- per-warp geometry: 16 warps = mq(8) x ch(2); warp = 64px x 32co ----
    const int mq   = wid >> 1;
    const int ch   = wid & 1;
    const int rloc = mq >> 1;               // local output row 0..3
    const int xh64 = (mq & 1) * 64;
    const int lrow = lane & 15;
    const int lcol = (lane >> 4) * 16;
    const uint32_t bxor = (uint32_t)((lane & 7) * 16);

    const float* biasp = g_bias + b * 64;

    for (int tile = 0; tile < 4; ++tile) {
        const int ty = ty0 + tile * 4;

        float acc[4][2][2][4];
        #pragma unroll
        for (int mt = 0; mt < 4; ++mt)
            #pragma unroll
            for (int pr = 0; pr < 2; ++pr)
                #pragma unroll
                for (int h = 0; h < 2; ++h)
                    #pragma unroll
                    for (int q = 0; q < 4; ++q) acc[mt][pr][h][q] = 0.0f;

        #pragma unroll 1
        for (int kh = 0; kh < 3; ++kh) {
            CP_WAIT0();
            __syncthreads();      // staged rows visible; prior phase reads done
            // prefetch: kh0 -> ty+3, kh1 -> ty+4, kh2 -> ty+5 & ty+6
            if (kh < 2) {
                const int pre = ty + 3 + kh;
                if (pre <= ty0 + 16) stage_row(pre);
            } else {
                if (ty + 5 <= ty0 + 16) stage_row(ty + 5);
                if (ty + 6 <= ty0 + 16) stage_row(ty + 6);
            }

            const uint32_t xt = xbase +
                (uint32_t)(((ty + rloc + kh) % NSLOT)) * X_TILE;   // (row+1)%7

            #pragma unroll
            for (int kw = 0; kw < 3; ++kw) {
                const int tap = kh * 3 + kw;
                const uint32_t wt = wbase + tap * 8192;
                const int arow0 = xh64 + lrow + kw;
                const uint32_t axor = (uint32_t)((arow0 & 7) * 16);

                #pragma unroll
                for (int k = 0; k < 4; ++k) {
                    uint32_t a4[4][4];
                    #pragma unroll
                    for (int mt = 0; mt < 4; ++mt) {
                        const uint32_t ad = (uint32_t)((arow0 + 16 * mt) * 128) +
                                            (((uint32_t)(k * 32 + lcol)) ^ axor);
                        ldsm4(a4[mt], xt + ad);
                    }
                    uint32_t bb[2][4];
                    #pragma unroll
                    for (int pr = 0; pr < 2; ++pr) {
                        const uint32_t bd = (uint32_t)(((ch * 2 + pr) * 16 + lrow) * 128) +
                                            (((uint32_t)(k * 32 + lcol)) ^ bxor);
                        ldsm4(bb[pr], wt + bd);
                    }
                    #pragma unroll
                    for (int mt = 0; mt < 4; ++mt)
                        #pragma unroll
                        for (int pr = 0; pr < 2; ++pr) {
                            mma16816(acc[mt][pr][0], a4[mt], bb[pr][0], bb[pr][2]);
                            mma16816(acc[mt][pr][1], a4[mt], bb[pr][1], bb[pr][3]);
                        }
                }
            }
        }

        // ---- epilogue: direct stores (bias + relu in regs) ----
        // Ring safety: next tile's first write is issued after its kh0
        // __syncthreads, which also orders these epilogue reads.
        const int y = ty + rloc;
        #pragma unroll
        for (int mt = 0; mt < 4; ++mt) {
            const int x0 = xh64 + mt * 16 + (lane >> 2);
            #pragma unroll
            for (int pr = 0; pr < 2; ++pr)
                #pragma unroll
                for (int h = 0; h < 2; ++h) {
                    const int co = ch * 32 + pr * 16 + h * 8 + (lane & 3) * 2;
                    const float b0v = biasp[co];
                    const float b1v = biasp[co + 1];
                    float* base = out + (((size_t)b * COUT + co) * HH + y) * WW;
                    base[x0]               = fmaxf(acc[mt][pr][h][0] + b0v, 0.0f);
                    base[WW * HH + x0]     = fmaxf(acc[mt][pr][h][1] + b1v, 0.0f);
                    base[x0 + 8]           = fmaxf(acc[mt][pr][h][2] + b0v, 0.0f);
                    base[WW * HH + x0 + 8] = fmaxf(acc[mt][pr][h][3] + b1v, 0.0f);
                }
        }
    }
}

// ---------------------------------------------------------------------------
extern "C" void kernel_launch(void* const* d_in, const int* in_sizes, int n_in,
                              void* d_out, int out_size) {
    const float* x  = (const float*)d_in[0];
    const float* z  = (const float*)d_in[1];
    const float* W0 = (const float*)d_in[2];
    const float* b0 = (const float*)d_in[3];
    const float* W1 = (const float*)d_in[4];
    const float* b1 = (const float*)d_in[5];
    const float* W2 = (const float*)d_in[6];
    const float* b2 = (const float*)d_in[7];
    float* out = (float*)d_out;

    cudaFuncSetAttribute(conv_mma_kernel,
                         cudaFuncAttributeMaxDynamicSharedMemorySize, SM_TOTAL);

    prep_kernel<<<2048 + (AWN + 255) / 256, 256>>>(x, z, W0, b0, W1, b1, W2, b2);
    {
        dim3 g(8, BB);
        conv_mma_kernel<<<g, 512, SM_TOTAL>>>(out);
    }
}

// round 14
// speedup vs baseline: 1.4983x; 1.4983x over previous
#include <cuda_runtime.h>
#include <cuda_fp16.h>
#include <cstdint>

// Problem constants
#define BB   16
#define CIN  64
#define COUT 64
#define HH   128
#define WW   128
#define NKW  36864
#define AWN  36928

// ---------------------------------------------------------------------------
// Device scratch (allocation-free rule)
// ---------------------------------------------------------------------------
__device__ float  g_bias[BB * COUT];
__device__ __half g_xh[BB * HH * WW * CIN];   // NHWC fp16
__device__ __half g_wh[BB * 9 * COUT * CIN];  // [b][tap][co][ci] fp16

// ---------------------------------------------------------------------------
// Helpers (family-agnostic: ldmatrix + mma.sync + cp.async, sm_80+)
// ---------------------------------------------------------------------------
__device__ __forceinline__ uint32_t smem_u32(const void* p) {
    uint32_t a;
    asm("{ .reg .u64 t; cvta.to.shared.u64 t, %1; cvt.u32.u64 %0, t; }" : "=r"(a) : "l"(p));
    return a;
}
__device__ __forceinline__ void ldsm4(uint32_t (&r)[4], uint32_t addr) {
    asm volatile("ldmatrix.sync.aligned.m8n8.x4.shared.b16 {%0,%1,%2,%3}, [%4];"
                 : "=r"(r[0]), "=r"(r[1]), "=r"(r[2]), "=r"(r[3]) : "r"(addr));
}
__device__ __forceinline__ void mma16816(float (&d)[4], const uint32_t (&a)[4],
                                         uint32_t b0, uint32_t b1) {
    asm volatile(
        "mma.sync.aligned.m16n8k16.row.col.f32.f16.f16.f32 "
        "{%0,%1,%2,%3}, {%4,%5,%6,%7}, {%8,%9}, {%0,%1,%2,%3};"
        : "+f"(d[0]), "+f"(d[1]), "+f"(d[2]), "+f"(d[3])
        : "r"(a[0]), "r"(a[1]), "r"(a[2]), "r"(a[3]), "r"(b0), "r"(b1));
}
__device__ __forceinline__ void cp16(uint32_t dst, const void* src, int sz) {
    asm volatile("cp.async.cg.shared.global [%0], [%1], 16, %2;"
                 :: "r"(dst), "l"(src), "r"(sz) : "memory");
}
#define CP_COMMIT() asm volatile("cp.async.commit_group;" ::: "memory")
#define CP_WAIT0()  asm volatile("cp.async.wait_group 0;" ::: "memory")

// ---------------------------------------------------------------------------
// Fused prep kernel: blocks [0,2048) transpose/pack x; blocks [2048,2193)
// run the MLP and pack weights + biases. Independent work, one launch.
// ---------------------------------------------------------------------------
__global__ __launch_bounds__(256) void prep_kernel(const float* __restrict__ x,
                                                   const float* __restrict__ z,
                                                   const float* __restrict__ W0,
                                                   const float* __restrict__ b0,
                                                   const float* __restrict__ W1,
                                                   const float* __restrict__ b1,
                                                   const float* __restrict__ W2,
                                                   const float* __restrict__ b2) {
    const int tid = threadIdx.x;

    if (blockIdx.x < 2048) {
        // ---- pack x: NCHW f32 -> NHWC fp16 (smem transpose) ----
        __shared__ float s[64][129];
        const int b = blockIdx.x >> 7;
        const int y = blockIdx.x & 127;
        const int px = tid & 127, hh = tid >> 7;
        #pragma unroll
        for (int it = 0; it < 32; ++it) {
            const int ci = it * 2 + hh;
            s[ci][px] = x[((size_t)(b * 64 + ci) * HH + y) * WW + px];
        }
        __syncthreads();
        const int ci2 = tid & 63, pg = tid >> 6;
        #pragma unroll
        for (int it = 0; it < 32; ++it) {
            const int p2 = it * 4 + pg;
            g_xh[((size_t)(b * HH + y) * WW + p2) * 64 + ci2] =
                __float2half_rn(s[ci2][p2]);
        }
        return;
    }

    // ---- MLP + weight pack ----
    __shared__ float sz[BB * 16];
    __shared__ float h0[BB * 20];
    __shared__ float sh[BB * 30];

    sz[tid] = z[tid];
    __syncthreads();
    for (int e = tid; e < BB * 20; e += 256) {
        const int b = e / 20, u = e % 20;
        float s = b0[u];
        #pragma unroll
        for (int j = 0; j < 16; ++j) s += sz[b * 16 + j] * W0[u * 16 + j];
        h0[e] = fmaxf(s, 0.0f);
    }
    __syncthreads();
    for (int e = tid; e < BB * 30; e += 256) {
        const int b = e / 30, u = e % 30;
        float s = b1[u];
        #pragma unroll
        for (int j = 0; j < 20; ++j) s += h0[b * 20 + j] * W1[u * 20 + j];
        sh[e] = fmaxf(s, 0.0f);
    }
    __syncthreads();

    const int i = (blockIdx.x - 2048) * 256 + tid;
    if (i >= AWN) return;
    float w[30];
    #pragma unroll
    for (int j = 0; j < 30; ++j) w[j] = W2[i * 30 + j];
    const float bias = b2[i];

    if (i < NKW) {
        const int co  = i / 576;
        const int rem = i % 576;
        const int ci  = rem / 9;
        const int s9  = rem % 9;
        #pragma unroll
        for (int b = 0; b < BB; ++b) {
            float s = bias;
            #pragma unroll
            for (int j = 0; j < 30; ++j) s += sh[b * 30 + j] * w[j];
            g_wh[((size_t)(b * 9 + s9) * 64 + co) * 64 + ci] =
                __float2half_rn(fmaxf(s, 0.0f));
        }
    } else {
        const int co = i - NKW;
        #pragma unroll
        for (int b = 0; b < BB; ++b) {
            float s = bias;
            #pragma unroll
            for (int j = 0; j < 30; ++j) s += sh[b * 30 + j] * w[j];
            g_bias[b * 64 + co] = fmaxf(s, 0.0f);
        }
    }
}

// ---------------------------------------------------------------------------
// Conv: EXACT R10 configuration (best measured: 106.8us total).
// Persistent-slab, rolling 5-slot x ring + cp.async, single fp16 pass.
// Grid: (8 slabs, 16 batch), 512 threads, 4 tiles of 4 output rows each.
// Warp = 64 px x 32 co (mt=4, pr=2). Weights (72KB, 9 taps) resident.
// kh0 stages ty+2 synchronously; kh0/kh1/kh2 prefetch one row ahead.
// ---------------------------------------------------------------------------
#define W_SMEM  73728                       // 9 taps * 8KB
#define X_TILE  16640                       // 130 rows * 128B
#define NSLOT   5
#define SM_TOTAL (W_SMEM + NSLOT * X_TILE)  // 156928

__global__ __launch_bounds__(512, 1) void conv_mma_kernel(float* __restrict__ out) {
    extern __shared__ char smem[];
    char* wptr = smem;
    char* xptr = smem + W_SMEM;
    const uint32_t wbase = smem_u32(wptr);
    const uint32_t xbase = smem_u32(xptr);

    const int tid  = threadIdx.x;
    const int wid  = tid >> 5;
    const int lane = tid & 31;
    const int slab = blockIdx.x;            // 0..7
    const int b    = blockIdx.y;
    const int ty0  = slab * 16;

    // ---- row stager: one image row -> ring slot, zero-fill OOB ----
    auto stage_row = [&](int rowimg) {
        const uint32_t slot = (uint32_t)((rowimg + 1) % NSLOT);
        const uint32_t sdst = xbase + slot * X_TILE;
        const int rc = min(max(rowimg, 0), HH - 1);
        for (int e = tid; e < 1040; e += 512) {
            const int r  = e >> 3;
            const int c  = e & 7;
            const int px = r - 1;
            const int pc = min(max(px, 0), WW - 1);
            const int sz = ((unsigned)rowimg < (unsigned)HH &&
                            (unsigned)px < (unsigned)WW) ? 16 : 0;
            const __half* src = g_xh + (((size_t)(b * HH + rc) * WW + pc) * 64 + c * 8);
            const uint32_t off = r * 128 + ((c * 16) ^ ((r & 7) * 16));
            cp16(sdst + off, src, sz);
        }
        CP_COMMIT();
    };

    // ---- stage ALL weights once (9 taps), swizzled [row=co][128B] ----
    for (int e = tid; e < 4608; e += 512) {
        const int chunk = e & 7;
        const int co    = (e >> 3) & 63;
        const int tap   = e >> 9;
        const __half* src = g_wh +
            (((size_t)(b * 9 + tap) * 64 + co) * 64 + chunk * 8);
        const uint32_t off = co * 128 + ((chunk * 16) ^ ((co & 7) * 16));
        *reinterpret_cast<uint4*>(wptr + tap * 8192 + off) =
            *reinterpret_cast<const uint4*>(src);
    }

    // prologue: rows ty0-1, ty0, ty0+1 in flight
    stage_row(ty0 - 1);
    stage_row(ty0);
    stage_row(ty0 + 1);

    // ---- per-warp geometry: 16 warps = mq(8) x ch(2); warp = 64px x 32co ----
    const int mq   = wid >> 1;
    const int ch   = wid & 1;
    const int rloc = mq >> 1;               // local output row 0..3
    const int xh64 = (mq & 1) * 64;
    const int lrow = lane & 15;
    const int lcol = (lane >> 4) * 16;
    const uint32_t bxor = (uint32_t)((lane & 7) * 16);

    const float* biasp = g_bias + b * 64;

    for (int tile = 0; tile < 4; ++tile) {
        const int ty = ty0 + tile * 4;

        float acc[4][2][2][4];
        #pragma unroll
        for (int mt = 0; mt < 4; ++mt)
            #pragma unroll
            for (int pr = 0; pr < 2; ++pr)
                #pragma unroll
                for (int h = 0; h < 2; ++h)
                    #pragma unroll
                    for (int q = 0; q < 4; ++q) acc[mt][pr][h][q] = 0.0f;

        #pragma unroll 1
        for (int kh = 0; kh < 3; ++kh) {
            // kh0: top row (ty+2) staged synchronously (its slot was read last tile)
            if (kh == 0) stage_row(ty + 2);
            CP_WAIT0();
            __syncthreads();
            // prefetch one row ahead, into the slot NOT read this phase
            const int pre = ty + 3 + kh;    // kh0->ty+3, kh1->ty+4, kh2->ty+5
            if (pre <= ty0 + 16) stage_row(pre);

            const uint32_t xt = xbase +
                (uint32_t)(((ty + rloc + kh) % NSLOT)) * X_TILE;   // (row+1)%5

            #pragma unroll
            for (int kw = 0; kw < 3; ++kw) {
                const int tap = kh * 3 + kw;
                const uint32_t wt = wbase + tap * 8192;
                const int arow0 = xh64 + lrow + kw;
                const uint32_t axor = (uint32_t)((arow0 & 7) * 16);

                #pragma unroll
                for (int k = 0; k < 4; ++k) {
                    uint32_t a4[4][4];
                    #pragma unroll
                    for (int mt = 0; mt < 4; ++mt) {
                        const uint32_t ad = (uint32_t)((arow0 + 16 * mt) * 128) +
                                            (((uint32_t)(k * 32 + lcol)) ^ axor);
                        ldsm4(a4[mt], xt + ad);
                    }
                    uint32_t bb[2][4];
                    #pragma unroll
                    for (int pr = 0; pr < 2; ++pr) {
                        const uint32_t bd = (uint32_t)(((ch * 2 + pr) * 16 + lrow) * 128) +
                                            (((uint32_t)(k * 32 + lcol)) ^ bxor);
                        ldsm4(bb[pr], wt + bd);
                    }
                    #pragma unroll
                    for (int mt = 0; mt < 4; ++mt)
                        #pragma unroll
                        for (int pr = 0; pr < 2; ++pr) {
                            mma16816(acc[mt][pr][0], a4[mt], bb[pr][0], bb[pr][2]);
                            mma16816(acc[mt][pr][1], a4[mt], bb[pr][1], bb[pr][3]);
                        }
                }
            }
        }

        // ---- epilogue: direct stores (bias + relu in regs) ----
        const int y = ty + rloc;
        #pragma unroll
        for (int mt = 0; mt < 4; ++mt) {
            const int x0 = xh64 + mt * 16 + (lane >> 2);
            #pragma unroll
            for (int pr = 0; pr < 2; ++pr)
                #pragma unroll
                for (int h = 0; h < 2; ++h) {
                    const int co = ch * 32 + pr * 16 + h * 8 + (lane & 3) * 2;
                    const float b0v = biasp[co];
                    const float b1v = biasp[co + 1];
                    float* base = out + (((size_t)b * COUT + co) * HH + y) * WW;
                    base[x0]               = fmaxf(acc[mt][pr][h][0] + b0v, 0.0f);
                    base[WW * HH + x0]     = fmaxf(acc[mt][pr][h][1] + b1v, 0.0f);
                    base[x0 + 8]           = fmaxf(acc[mt][pr][h][2] + b0v, 0.0f);
                    base[WW * HH + x0 + 8] = fmaxf(acc[mt][pr][h][3] + b1v, 0.0f);
                }
        }
        __syncthreads();   // all phases' reads done before next tile overwrites ring
    }
}

// ---------------------------------------------------------------------------
extern "C" void kernel_launch(void* const* d_in, const int* in_sizes, int n_in,
                              void* d_out, int out_size) {
    const float* x  = (const float*)d_in[0];
    const float* z  = (const float*)d_in[1];
    const float* W0 = (const float*)d_in[2];
    const float* b0 = (const float*)d_in[3];
    const float* W1 = (const float*)d_in[4];
    const float* b1 = (const float*)d_in[5];
    const float* W2 = (const float*)d_in[6];
    const float* b2 = (const float*)d_in[7];
    float* out = (float*)d_out;

    cudaFuncSetAttribute(conv_mma_kernel,
                         cudaFuncAttributeMaxDynamicSharedMemorySize, SM_TOTAL);

    prep_kernel<<<2048 + (AWN + 255) / 256, 256>>>(x, z, W0, b0, W1, b1, W2, b2);
    {
        dim3 g(8, BB);
        conv_mma_kernel<<<g, 512, SM_TOTAL>>>(out);
    }
}